// round 15
// baseline (speedup 1.0000x reference)
#include <cuda_runtime.h>

// Gray-Scott residual: 8 outputs/thread (z-pair x x-pair x y-pair),
// float2 loads, z-edges via warp shuffle, taps shared across x and y pairs.
// R15 = R14 with __launch_bounds__(256,6): reg cap 40 -> 6 blocks/SM (75% occ).
// Input: output (50,2,100,100,100) fp32. Output: f_u(48,96,96,96) ++ f_v.

#define TOUT 48
#define D 96
#define IN_T 2000000
#define IN_C 1000000
#define IN_Y 10000
#define IN_X 100
#define N_OUT (TOUT * D * D * D)       // 42467328
#define NTHREADS (N_OUT / 8)           // 5308416

__device__ __forceinline__ float2 ldg2(const float* p) {
    return __ldg((const float2*)p);
}
__device__ __forceinline__ float2 shup(float2 v) {
    float2 r;
    r.x = __shfl_up_sync(0xffffffffu, v.x, 1);
    r.y = __shfl_up_sync(0xffffffffu, v.y, 1);
    return r;
}
__device__ __forceinline__ float2 shdn(float2 v) {
    float2 r;
    r.x = __shfl_down_sync(0xffffffffu, v.x, 1);
    r.y = __shfl_down_sync(0xffffffffu, v.y, 1);
    return r;
}

__global__ void __launch_bounds__(256, 6) gs15(
    const float* __restrict__ in, float* __restrict__ out)
{
    int idx = blockIdx.x * 256 + threadIdx.x;
    if (idx >= NTHREADS) return;

    int zp = idx % 48;  int q = idx / 48;
    int xp = q % 48;    q /= 48;
    int yp = q % 48;    int t = q / 48;

    const int zi = 2 * zp, xi = 2 * xp, yi = 2 * yp;

    // center point (r=0, xr=0): input (t, ch, yi+2, xi+2, zi+2)
    const float* P = in + t * IN_T + (yi + 2) * IN_Y + (xi + 2) * IN_X + (zi + 2);

    const unsigned lane = threadIdx.x & 31u;
    const bool hu = (lane > 0)  && (zp > 0);
    const bool hd = (lane < 31) && (zp < 47);

    const float INV_DX2 = 2304.0f / 10000.0f;
    const float C1 = 4.0f / 3.0f;
    const float C2 = -1.0f / 12.0f;
    const float C0 = -7.5f;

    // carried u-pass results: centers + partial f_u for 8 points
    float2 cu[2][2], pu[2][2];

    #pragma unroll
    for (int ch = 0; ch < 2; ch++) {
        const float* p = P + ch * IN_C;

        // centers: [y-row r][x-row xr]
        float2 c[2][2];
        c[0][0] = ldg2(p);
        c[0][1] = ldg2(p + IN_X);
        c[1][0] = ldg2(p + IN_Y);
        c[1][1] = ldg2(p + IN_Y + IN_X);

        // z-window edges via shuffle; boundary fallback loads
        float2 wl[2][2], wr[2][2];
        #pragma unroll
        for (int r = 0; r < 2; r++)
            #pragma unroll
            for (int xr = 0; xr < 2; xr++) {
                wl[r][xr] = shup(c[r][xr]);
                wr[r][xr] = shdn(c[r][xr]);
            }
        if (!hu) {
            wl[0][0] = ldg2(p - 2);
            wl[0][1] = ldg2(p + IN_X - 2);
            wl[1][0] = ldg2(p + IN_Y - 2);
            wl[1][1] = ldg2(p + IN_Y + IN_X - 2);
        }
        if (!hd) {
            wr[0][0] = ldg2(p + 2);
            wr[0][1] = ldg2(p + IN_X + 2);
            wr[1][0] = ldg2(p + IN_Y + 2);
            wr[1][1] = ldg2(p + IN_Y + IN_X + 2);
        }

        // x-taps per y-row: tap-only rows x = xi, xi+1, xi+4, xi+5
        float2 Xt[2][4];
        #pragma unroll
        for (int r = 0; r < 2; r++) {
            const float* pr = p + r * IN_Y;
            Xt[r][0] = ldg2(pr - 2 * IN_X);
            Xt[r][1] = ldg2(pr - IN_X);
            Xt[r][2] = ldg2(pr + 2 * IN_X);
            Xt[r][3] = ldg2(pr + 3 * IN_X);
        }

        // y-taps per x-row: tap-only rows y = yi, yi+1, yi+4, yi+5
        float2 Yt[2][4];
        #pragma unroll
        for (int xr = 0; xr < 2; xr++) {
            const float* pr = p + xr * IN_X;
            Yt[xr][0] = ldg2(pr - 2 * IN_Y);
            Yt[xr][1] = ldg2(pr - IN_Y);
            Yt[xr][2] = ldg2(pr + 2 * IN_Y);
            Yt[xr][3] = ldg2(pr + 3 * IN_Y);
        }

        #pragma unroll
        for (int r = 0; r < 2; r++) {
            #pragma unroll
            for (int xr = 0; xr < 2; xr++) {
                float2 cc = c[r][xr];
                float2 l = wl[r][xr], w = wr[r][xr];

                float2 xm1 = (xr == 0) ? Xt[r][1] : c[r][0];
                float2 xq1 = (xr == 0) ? c[r][1]  : Xt[r][2];
                float2 xm2 = (xr == 0) ? Xt[r][0] : Xt[r][1];
                float2 xq2 = (xr == 0) ? Xt[r][2] : Xt[r][3];

                float2 ym1 = (r == 0) ? Yt[xr][1] : c[0][xr];
                float2 yq1 = (r == 0) ? c[1][xr]  : Yt[xr][2];
                float2 ym2 = (r == 0) ? Yt[xr][0] : Yt[xr][1];
                float2 yq2 = (r == 0) ? Yt[xr][2] : Yt[xr][3];

                float s1x = l.y + cc.y + xm1.x + xq1.x + ym1.x + yq1.x;
                float s2x = l.x + w.x + xm2.x + xq2.x + ym2.x + yq2.x;
                float s1y = cc.x + w.x + xm1.y + xq1.y + ym1.y + yq1.y;
                float s2y = l.y + w.y + xm2.y + xq2.y + ym2.y + yq2.y;

                float lapx = (C0 * cc.x + C1 * s1x + C2 * s2x) * INV_DX2;
                float lapy = (C0 * cc.y + C1 * s1y + C2 * s2y) * INV_DX2;

                // t+1 center loaded late to shorten live range
                const float* pn = p + IN_T + r * IN_Y + xr * IN_X;
                float2 n = ldg2(pn);

                if (ch == 0) {
                    cu[r][xr] = cc;
                    pu[r][xr].x = 0.2f * lapx + 0.025f * (1.0f - cc.x)
                                - (n.x - cc.x) * 2.0f;
                    pu[r][xr].y = 0.2f * lapy + 0.025f * (1.0f - cc.y)
                                - (n.y - cc.y) * 2.0f;
                } else {
                    float uvx = cu[r][xr].x * cc.x * cc.x;
                    float uvy = cu[r][xr].y * cc.y * cc.y;
                    float2 fu, fv;
                    fu.x = pu[r][xr].x - uvx;
                    fu.y = pu[r][xr].y - uvy;
                    fv.x = 0.1f * lapx + uvx - 0.08f * cc.x - (n.x - cc.x) * 2.0f;
                    fv.y = 0.1f * lapy + uvy - 0.08f * cc.y - (n.y - cc.y) * 2.0f;

                    int o = ((t * D + yi + r) * D + xi + xr) * D + zi;
                    *(float2*)(out + o)         = fu;
                    *(float2*)(out + o + N_OUT) = fv;
                }
            }
        }
    }
}

extern "C" void kernel_launch(void* const* d_in, const int* in_sizes, int n_in,
                              void* d_out, int out_size)
{
    const float* in = (const float*)d_in[0];
    float* out = (float*)d_out;
    int blocks = (NTHREADS + 255) / 256;   // 20736
    gs15<<<blocks, 256>>>(in, out);
}

// round 16
// speedup vs baseline: 1.0993x; 1.0993x over previous
#include <cuda_runtime.h>

// Gray-Scott residual: 4 outputs/thread (z-pair x y-pair), float2 loads,
// z-window edges via warp shuffle, y-taps shared across the y-pair.
// R16 = R8 + exact grid (no bounds check) + streaming stores (__stcs)
//     + t+1 loads batched with taps.
// Input: output (50,2,100,100,100) fp32. Output: f_u(48,96,96,96) ++ f_v.

#define TOUT 48
#define D 96
#define IN_T 2000000
#define IN_C 1000000
#define IN_Y 10000
#define IN_X 100
#define N_OUT (TOUT * D * D * D)       // 42467328
#define NTHREADS (N_OUT / 4)           // 10616832 = 41472 * 256 exactly

__device__ __forceinline__ float2 ldg2(const float* p) {
    return __ldg((const float2*)p);
}
__device__ __forceinline__ void stcs2(float* p, float2 v) {
    __stcs((float2*)p, v);
}
__device__ __forceinline__ float2 shfl_up2(float2 v) {
    float2 r;
    r.x = __shfl_up_sync(0xffffffffu, v.x, 1);
    r.y = __shfl_up_sync(0xffffffffu, v.y, 1);
    return r;
}
__device__ __forceinline__ float2 shfl_dn2(float2 v) {
    float2 r;
    r.x = __shfl_down_sync(0xffffffffu, v.x, 1);
    r.y = __shfl_down_sync(0xffffffffu, v.y, 1);
    return r;
}

__global__ void __launch_bounds__(256, 6) gs16(
    const float* __restrict__ in, float* __restrict__ out)
{
    int idx = blockIdx.x * 256 + threadIdx.x;   // grid is exact; no bound check

    int zp = idx % (D / 2);            // z pair: outputs z = 2zp, 2zp+1
    int r  = idx / (D / 2);
    int x  = r % D;
    r /= D;
    int y2 = r % (D / 2);              // y pair: outputs y = 2y2, 2y2+1
    int t  = r / (D / 2);
    int y  = 2 * y2;

    const float* P = in + t * IN_T + (y + 2) * IN_Y + (x + 2) * IN_X + (2 * zp + 2);

    const unsigned lane = threadIdx.x & 31u;
    const bool haveUp = (lane > 0)  && (zp > 0);
    const bool haveDn = (lane < 31) && (zp < (D / 2 - 1));

    const float INV_DX2 = 2304.0f / 10000.0f;
    const float C1 = 4.0f / 3.0f;
    const float C2 = -1.0f / 12.0f;
    const float C0 = -7.5f;

    // carried across channel passes: u centers + partial f_u (4 pts)
    float cu0x, cu0y, cu1x, cu1y;
    float pu0x, pu0y, pu1x, pu1y;

    #pragma unroll
    for (int ch = 0; ch < 2; ch++) {
        const float* p = P + ch * IN_C;

        // centers: rows y_in = y+2 (pt row 0) and y+3 (pt row 1)
        float2 c0 = ldg2(p);
        float2 c1 = ldg2(p + IN_Y);

        // x-taps, both rows (front-batched for MLP)
        float2 xm1_0 = ldg2(p - IN_X),            xp1_0 = ldg2(p + IN_X);
        float2 xm2_0 = ldg2(p - 2 * IN_X),        xp2_0 = ldg2(p + 2 * IN_X);
        float2 xm1_1 = ldg2(p + IN_Y - IN_X),     xp1_1 = ldg2(p + IN_Y + IN_X);
        float2 xm2_1 = ldg2(p + IN_Y - 2 * IN_X), xp2_1 = ldg2(p + IN_Y + 2 * IN_X);

        // shared y-taps: rows y_in = y, y+1, y+4, y+5
        float2 a = ldg2(p - 2 * IN_Y);   // y_in = y
        float2 b = ldg2(p - IN_Y);       // y_in = y+1
        float2 d = ldg2(p + 2 * IN_Y);   // y_in = y+4
        float2 e = ldg2(p + 3 * IN_Y);   // y_in = y+5

        // t+1 centers (batched with taps, not late)
        float2 n0 = ldg2(p + IN_T);
        float2 n1 = ldg2(p + IN_T + IN_Y);

        // z-window edges via shuffle (fallback loads at boundaries)
        float2 w00 = shfl_up2(c0), w20 = shfl_dn2(c0);
        float2 w01 = shfl_up2(c1), w21 = shfl_dn2(c1);
        if (!haveUp) { w00 = ldg2(p - 2); w01 = ldg2(p + IN_Y - 2); }
        if (!haveDn) { w20 = ldg2(p + 2); w21 = ldg2(p + IN_Y + 2); }

        // point row 0 (center c0): ym1=b, ym2=a, yp1=c1, yp2=d
        float s1_0x = w00.y + c0.y + xm1_0.x + xp1_0.x + b.x + c1.x;
        float s2_0x = w00.x + w20.x + xm2_0.x + xp2_0.x + a.x + d.x;
        float s1_0y = c0.x + w20.x + xm1_0.y + xp1_0.y + b.y + c1.y;
        float s2_0y = w00.y + w20.y + xm2_0.y + xp2_0.y + a.y + d.y;
        // point row 1 (center c1): ym1=c0, ym2=b, yp1=d, yp2=e
        float s1_1x = w01.y + c1.y + xm1_1.x + xp1_1.x + c0.x + d.x;
        float s2_1x = w01.x + w21.x + xm2_1.x + xp2_1.x + b.x + e.x;
        float s1_1y = c1.x + w21.x + xm1_1.y + xp1_1.y + c0.y + d.y;
        float s2_1y = w01.y + w21.y + xm2_1.y + xp2_1.y + b.y + e.y;

        float lap0x = (C0 * c0.x + C1 * s1_0x + C2 * s2_0x) * INV_DX2;
        float lap0y = (C0 * c0.y + C1 * s1_0y + C2 * s2_0y) * INV_DX2;
        float lap1x = (C0 * c1.x + C1 * s1_1x + C2 * s2_1x) * INV_DX2;
        float lap1y = (C0 * c1.y + C1 * s1_1y + C2 * s2_1y) * INV_DX2;

        if (ch == 0) {
            // u pass: partial f_u = DU*lap - u_t + FF*(1-u)  (uv2 added later)
            cu0x = c0.x; cu0y = c0.y; cu1x = c1.x; cu1y = c1.y;
            pu0x = 0.2f * lap0x + 0.025f * (1.0f - c0.x) - (n0.x - c0.x) * 2.0f;
            pu0y = 0.2f * lap0y + 0.025f * (1.0f - c0.y) - (n0.y - c0.y) * 2.0f;
            pu1x = 0.2f * lap1x + 0.025f * (1.0f - c1.x) - (n1.x - c1.x) * 2.0f;
            pu1y = 0.2f * lap1y + 0.025f * (1.0f - c1.y) - (n1.y - c1.y) * 2.0f;
        } else {
            // v pass: finalize everything; streaming stores (output never re-read)
            float uv0x = cu0x * c0.x * c0.x;
            float uv0y = cu0y * c0.y * c0.y;
            float uv1x = cu1x * c1.x * c1.x;
            float uv1y = cu1y * c1.y * c1.y;

            float2 fu0 = make_float2(pu0x - uv0x, pu0y - uv0y);
            float2 fu1 = make_float2(pu1x - uv1x, pu1y - uv1y);
            float2 fv0, fv1;
            fv0.x = 0.1f * lap0x + uv0x - 0.08f * c0.x - (n0.x - c0.x) * 2.0f;
            fv0.y = 0.1f * lap0y + uv0y - 0.08f * c0.y - (n0.y - c0.y) * 2.0f;
            fv1.x = 0.1f * lap1x + uv1x - 0.08f * c1.x - (n1.x - c1.x) * 2.0f;
            fv1.y = 0.1f * lap1y + uv1y - 0.08f * c1.y - (n1.y - c1.y) * 2.0f;

            int o0 = ((t * D + y) * D + x) * D + 2 * zp;
            int o1 = o0 + D * D;               // y+1 row
            stcs2(out + o0,         fu0);
            stcs2(out + o1,         fu1);
            stcs2(out + o0 + N_OUT, fv0);
            stcs2(out + o1 + N_OUT, fv1);
        }
    }
}

extern "C" void kernel_launch(void* const* d_in, const int* in_sizes, int n_in,
                              void* d_out, int out_size)
{
    const float* in = (const float*)d_in[0];
    float* out = (float*)d_out;
    gs16<<<NTHREADS / 256, 256>>>(in, out);   // 41472 blocks, exact
}

// round 17
// speedup vs baseline: 1.2113x; 1.1019x over previous
#include <cuda_runtime.h>

// Gray-Scott residual: 4 outputs/thread (z-pair x y-pair), float2 loads,
// z-window edges via warp shuffle, y-taps shared across the y-pair.
// R17 = R8 verbatim (the 161.9us champion), exact grid so no bounds check.
// Input: output (50,2,100,100,100) fp32. Output: f_u(48,96,96,96) ++ f_v.

#define TOUT 48
#define D 96
#define IN_T 2000000
#define IN_C 1000000
#define IN_Y 10000
#define IN_X 100
#define N_OUT (TOUT * D * D * D)       // 42467328
#define NTHREADS (N_OUT / 4)           // 10616832 = 41472 * 256 exactly

__device__ __forceinline__ float2 ldg2(const float* p) {
    return __ldg((const float2*)p);
}
__device__ __forceinline__ float2 shfl_up2(float2 v) {
    float2 r;
    r.x = __shfl_up_sync(0xffffffffu, v.x, 1);
    r.y = __shfl_up_sync(0xffffffffu, v.y, 1);
    return r;
}
__device__ __forceinline__ float2 shfl_dn2(float2 v) {
    float2 r;
    r.x = __shfl_down_sync(0xffffffffu, v.x, 1);
    r.y = __shfl_down_sync(0xffffffffu, v.y, 1);
    return r;
}

__global__ void __launch_bounds__(256, 6) gs17(
    const float* __restrict__ in, float* __restrict__ out)
{
    int idx = blockIdx.x * 256 + threadIdx.x;   // grid exact; no bounds check

    int zp = idx % (D / 2);            // z pair: outputs z = 2zp, 2zp+1
    int r  = idx / (D / 2);
    int x  = r % D;
    r /= D;
    int y2 = r % (D / 2);              // y pair: outputs y = 2y2, 2y2+1
    int t  = r / (D / 2);
    int y  = 2 * y2;

    const float* P = in + t * IN_T + (y + 2) * IN_Y + (x + 2) * IN_X + (2 * zp + 2);

    const unsigned lane = threadIdx.x & 31u;
    const bool haveUp = (lane > 0)  && (zp > 0);
    const bool haveDn = (lane < 31) && (zp < (D / 2 - 1));

    const float INV_DX2 = 2304.0f / 10000.0f;
    const float C1 = 4.0f / 3.0f;
    const float C2 = -1.0f / 12.0f;
    const float C0 = -7.5f;

    // carried across channel passes: u centers + partial f_u (4 pts)
    float cu0x, cu0y, cu1x, cu1y;
    float pu0x, pu0y, pu1x, pu1y;

    #pragma unroll
    for (int ch = 0; ch < 2; ch++) {
        const float* p = P + ch * IN_C;

        // centers: rows y_in = y+2 (pt row 0) and y+3 (pt row 1)
        float2 c0 = ldg2(p);
        float2 c1 = ldg2(p + IN_Y);

        // z-window edges via shuffle (fallback loads at boundaries)
        float2 w00 = shfl_up2(c0), w20 = shfl_dn2(c0);
        float2 w01 = shfl_up2(c1), w21 = shfl_dn2(c1);
        if (!haveUp) { w00 = ldg2(p - 2); w01 = ldg2(p + IN_Y - 2); }
        if (!haveDn) { w20 = ldg2(p + 2); w21 = ldg2(p + IN_Y + 2); }

        // x-taps, both rows
        float2 xm1_0 = ldg2(p - IN_X),            xp1_0 = ldg2(p + IN_X);
        float2 xm2_0 = ldg2(p - 2 * IN_X),        xp2_0 = ldg2(p + 2 * IN_X);
        float2 xm1_1 = ldg2(p + IN_Y - IN_X),     xp1_1 = ldg2(p + IN_Y + IN_X);
        float2 xm2_1 = ldg2(p + IN_Y - 2 * IN_X), xp2_1 = ldg2(p + IN_Y + 2 * IN_X);

        // shared y-taps: rows y_in = y, y+1, y+4, y+5
        float2 a = ldg2(p - 2 * IN_Y);   // y_in = y
        float2 b = ldg2(p - IN_Y);       // y_in = y+1
        float2 d = ldg2(p + 2 * IN_Y);   // y_in = y+4
        float2 e = ldg2(p + 3 * IN_Y);   // y_in = y+5

        // t+1 centers
        float2 n0 = ldg2(p + IN_T);
        float2 n1 = ldg2(p + IN_T + IN_Y);

        // point row 0 (center c0): ym1=b, ym2=a, yp1=c1, yp2=d
        float s1_0x = w00.y + c0.y + xm1_0.x + xp1_0.x + b.x + c1.x;
        float s2_0x = w00.x + w20.x + xm2_0.x + xp2_0.x + a.x + d.x;
        float s1_0y = c0.x + w20.x + xm1_0.y + xp1_0.y + b.y + c1.y;
        float s2_0y = w00.y + w20.y + xm2_0.y + xp2_0.y + a.y + d.y;
        // point row 1 (center c1): ym1=c0, ym2=b, yp1=d, yp2=e
        float s1_1x = w01.y + c1.y + xm1_1.x + xp1_1.x + c0.x + d.x;
        float s2_1x = w01.x + w21.x + xm2_1.x + xp2_1.x + b.x + e.x;
        float s1_1y = c1.x + w21.x + xm1_1.y + xp1_1.y + c0.y + d.y;
        float s2_1y = w01.y + w21.y + xm2_1.y + xp2_1.y + b.y + e.y;

        float lap0x = (C0 * c0.x + C1 * s1_0x + C2 * s2_0x) * INV_DX2;
        float lap0y = (C0 * c0.y + C1 * s1_0y + C2 * s2_0y) * INV_DX2;
        float lap1x = (C0 * c1.x + C1 * s1_1x + C2 * s2_1x) * INV_DX2;
        float lap1y = (C0 * c1.y + C1 * s1_1y + C2 * s2_1y) * INV_DX2;

        if (ch == 0) {
            // u pass: partial f_u = DU*lap - u_t + FF*(1-u)  (uv2 added later)
            cu0x = c0.x; cu0y = c0.y; cu1x = c1.x; cu1y = c1.y;
            pu0x = 0.2f * lap0x + 0.025f * (1.0f - c0.x) - (n0.x - c0.x) * 2.0f;
            pu0y = 0.2f * lap0y + 0.025f * (1.0f - c0.y) - (n0.y - c0.y) * 2.0f;
            pu1x = 0.2f * lap1x + 0.025f * (1.0f - c1.x) - (n1.x - c1.x) * 2.0f;
            pu1y = 0.2f * lap1y + 0.025f * (1.0f - c1.y) - (n1.y - c1.y) * 2.0f;
        } else {
            // v pass: finalize everything
            float uv0x = cu0x * c0.x * c0.x;
            float uv0y = cu0y * c0.y * c0.y;
            float uv1x = cu1x * c1.x * c1.x;
            float uv1y = cu1y * c1.y * c1.y;

            float2 fu0 = make_float2(pu0x - uv0x, pu0y - uv0y);
            float2 fu1 = make_float2(pu1x - uv1x, pu1y - uv1y);
            float2 fv0, fv1;
            fv0.x = 0.1f * lap0x + uv0x - 0.08f * c0.x - (n0.x - c0.x) * 2.0f;
            fv0.y = 0.1f * lap0y + uv0y - 0.08f * c0.y - (n0.y - c0.y) * 2.0f;
            fv1.x = 0.1f * lap1x + uv1x - 0.08f * c1.x - (n1.x - c1.x) * 2.0f;
            fv1.y = 0.1f * lap1y + uv1y - 0.08f * c1.y - (n1.y - c1.y) * 2.0f;

            int o0 = ((t * D + y) * D + x) * D + 2 * zp;
            int o1 = o0 + D * D;               // y+1 row
            *(float2*)(out + o0)             = fu0;
            *(float2*)(out + o1)             = fu1;
            *(float2*)(out + o0 + N_OUT)     = fv0;
            *(float2*)(out + o1 + N_OUT)     = fv1;
        }
    }
}

extern "C" void kernel_launch(void* const* d_in, const int* in_sizes, int n_in,
                              void* d_out, int out_size)
{
    const float* in = (const float*)d_in[0];
    float* out = (float*)d_out;
    gs17<<<NTHREADS / 256, 256>>>(in, out);   // 41472 blocks, exact
}